// round 15
// baseline (speedup 1.0000x reference)
#include <cuda_runtime.h>

#define BATCH 65536
#define CEN   10
#define DIM   384
#define HID   768
#define D4    96

#define PHI_OFF ((size_t)BATCH * DIM)
#define TGT_OFF ((size_t)BATCH * DIM + (size_t)BATCH * CEN)

__device__ float  g_center[CEN * DIM];
__device__ float  g_colsum[CEN];
__device__ float4 g_part4[24 * CEN * D4];

// packed f32x2 helpers
#define FMA2(d, a, b, c_) \
    asm("fma.rn.f32x2 %0, %1, %2, %3;" : "=l"(d) : "l"(a), "l"(b), "l"(c_))
__device__ __forceinline__ float upk_sum(unsigned long long v) {
    float lo, hi;
    asm("mov.b64 {%0, %1}, %2;" : "=f"(lo), "=f"(hi) : "l"(v));
    return lo + hi;
}

// ---------------------------------------------------------------------------
// K1a: split-K partial GEMM for Center. 24 blocks x 384 threads. (R6 exact)
// ---------------------------------------------------------------------------
__global__ __launch_bounds__(384)
void k_center1(const float* __restrict__ M, const float* __restrict__ W1) {
    __shared__ float  sM[CEN][32];
    __shared__ float4 sAcc[4][CEN][D4];

    int tid = threadIdx.x;
    int hs  = tid / 96;
    int d4  = tid % 96;
    int h0  = blockIdx.x * 32;

    if (tid < 320) {
        int c = tid / 32, hl = tid % 32;
        sM[c][hl] = __ldg(M + c * HID + h0 + hl);
    }
    __syncthreads();

    float4 acc[CEN];
#pragma unroll
    for (int c = 0; c < CEN; c++) acc[c] = make_float4(0.f, 0.f, 0.f, 0.f);

    const float4* W4 = (const float4*)W1;
#pragma unroll
    for (int i = 0; i < 8; i++) {
        int hl = hs * 8 + i;
        float4 w = __ldg(&W4[(size_t)(h0 + hl) * D4 + d4]);
#pragma unroll
        for (int c = 0; c < CEN; c++) {
            float m = sM[c][hl];
            acc[c].x += m * w.x; acc[c].y += m * w.y;
            acc[c].z += m * w.z; acc[c].w += m * w.w;
        }
    }
#pragma unroll
    for (int c = 0; c < CEN; c++) sAcc[hs][c][d4] = acc[c];
    __syncthreads();

    if (hs == 0) {
#pragma unroll
        for (int c = 0; c < CEN; c++) {
            float4 a = sAcc[0][c][d4], b = sAcc[1][c][d4];
            float4 e = sAcc[2][c][d4], f = sAcc[3][c][d4];
            float4 s;
            s.x = (a.x + b.x) + (e.x + f.x);
            s.y = (a.y + b.y) + (e.y + f.y);
            s.z = (a.z + b.z) + (e.z + f.z);
            s.w = (a.w + b.w) + (e.w + f.w);
            g_part4[((size_t)blockIdx.x * CEN + c) * D4 + d4] = s;
        }
    }
}

// ---------------------------------------------------------------------------
// K1b: reduce partials + bias + LeakyReLU + /384; zero colsum. (R6 exact)
// ---------------------------------------------------------------------------
__global__ void k_center2(const float* __restrict__ b1) {
    int j = blockIdx.x * 256 + threadIdx.x;
    if (j < CEN * DIM) {
        const float* gp = (const float*)g_part4;
        float s = 0.f;
#pragma unroll
        for (int k = 0; k < 24; k++) s += gp[k * (CEN * DIM) + j];
        int d = j % DIM;
        float v = s + __ldg(b1 + d);
        v = (v >= 0.f) ? v : 0.01f * v;
        g_center[j] = v * (1.0f / 384.0f);
    }
    if (blockIdx.x == 0 && threadIdx.x < CEN) g_colsum[threadIdx.x] = 0.f;
}

// ---------------------------------------------------------------------------
// K2: phi + ct + colsum (R6 exact: R=4, 128 thr, 4 CTA/SM, plain-float ct,
// .cs streams, colsum last).
// ---------------------------------------------------------------------------
__global__ __launch_bounds__(128, 4)
void k_phi_ct(const float* __restrict__ Ztd, float* __restrict__ out,
              const int* __restrict__ weighted) {
    __shared__ float4 sC[CEN * D4];
    __shared__ float  scn[CEN];
    __shared__ float  sred[4][CEN];

    int tid = threadIdx.x, lane = tid & 31, wid = tid >> 5;
    int q = lane & 3;
    int g = lane >> 2;

    const float4* gc4 = (const float4*)g_center;
    for (int i = tid; i < CEN * D4; i += 128) sC[i] = gc4[i];
    __syncthreads();

    for (int c = wid; c < CEN; c += 4) {
        float s = 0.f;
#pragma unroll
        for (int k = 0; k < 3; k++) {
            float4 v = sC[c * D4 + lane + 32 * k];
            s += v.x * v.x + v.y * v.y + v.z * v.z + v.w * v.w;
        }
#pragma unroll
        for (int o = 16; o; o >>= 1) s += __shfl_xor_sync(0xffffffffu, s, o);
        if (lane == 0) scn[c] = s;
    }
    __syncthreads();

    int row0 = blockIdx.x * 128 + wid * 32 + g * 4;
    const char* Zb = (const char*)Ztd;
    const char* pr0 = Zb + ((size_t)(row0 + 0) * D4 + q) * 16;
    const char* pr1 = Zb + ((size_t)(row0 + 1) * D4 + q) * 16;
    const char* pr2 = Zb + ((size_t)(row0 + 2) * D4 + q) * 16;
    const char* pr3 = Zb + ((size_t)(row0 + 3) * D4 + q) * 16;
    const ulonglong2* sC2 = (const ulonglong2*)sC;

    unsigned long long dp2[4][CEN];
    unsigned long long zz2[4];
#pragma unroll
    for (int r = 0; r < 4; r++) {
        zz2[r] = 0ull;
#pragma unroll
        for (int c = 0; c < CEN; c++) dp2[r][c] = 0ull;
    }

#pragma unroll 4
    for (int k = 0; k < 24; k++) {
        unsigned long long za[4], zb[4];
        asm("ld.global.cs.v2.u64 {%0, %1}, [%2];" : "=l"(za[0]), "=l"(zb[0]) : "l"(pr0 + k * 64));
        asm("ld.global.cs.v2.u64 {%0, %1}, [%2];" : "=l"(za[1]), "=l"(zb[1]) : "l"(pr1 + k * 64));
        asm("ld.global.cs.v2.u64 {%0, %1}, [%2];" : "=l"(za[2]), "=l"(zb[2]) : "l"(pr2 + k * 64));
        asm("ld.global.cs.v2.u64 {%0, %1}, [%2];" : "=l"(za[3]), "=l"(zb[3]) : "l"(pr3 + k * 64));
#pragma unroll
        for (int r = 0; r < 4; r++) {
            FMA2(zz2[r], za[r], za[r], zz2[r]);
            FMA2(zz2[r], zb[r], zb[r], zz2[r]);
        }
#pragma unroll
        for (int c = 0; c < CEN; c++) {
            ulonglong2 cv = sC2[c * D4 + k * 4 + q];
#pragma unroll
            for (int r = 0; r < 4; r++) {
                FMA2(dp2[r][c], za[r], cv.x, dp2[r][c]);
                FMA2(dp2[r][c], zb[r], cv.y, dp2[r][c]);
            }
        }
    }

    float zz[4], dp[4][CEN];
#pragma unroll
    for (int r = 0; r < 4; r++) {
        zz[r] = upk_sum(zz2[r]);
#pragma unroll
        for (int c = 0; c < CEN; c++) dp[r][c] = upk_sum(dp2[r][c]);
    }

#pragma unroll
    for (int o = 1; o <= 2; o <<= 1) {
#pragma unroll
        for (int r = 0; r < 4; r++) {
            zz[r] += __shfl_xor_sync(0xffffffffu, zz[r], o);
#pragma unroll
            for (int c = 0; c < CEN; c++)
                dp[r][c] += __shfl_xor_sync(0xffffffffu, dp[r][c], o);
        }
    }

    float phi_all[4][CEN];
#pragma unroll
    for (int r = 0; r < 4; r++) {
        float nu[CEN], den = 0.f;
#pragma unroll
        for (int c = 0; c < CEN; c++) {
            float n = zz[r] - 2.f * dp[r][c] + scn[c];
            nu[c] = __fdividef(1.f, 1.f + n);
            den += nu[c];
        }
        float inv = __fdividef(1.f, den);
#pragma unroll
        for (int c = 0; c < CEN; c++) phi_all[r][c] = nu[c] * inv;

        float2* p2 = (float2*)(out + PHI_OFF + (size_t)(row0 + r) * CEN);
        p2[q] = make_float2(phi_all[r][2 * q], phi_all[r][2 * q + 1]);
        if (q == 0) p2[4] = make_float2(phi_all[r][8], phi_all[r][9]);
    }

    // ---- ct in-place ----
    float4* ct4 = (float4*)out;
    int w = *weighted;
    if (w) {
#pragma unroll 2
        for (int k = 0; k < 24; k++) {
            int cd = k * 4 + q;
            float4 acc[4];
#pragma unroll
            for (int r = 0; r < 4; r++) acc[r] = make_float4(0.f, 0.f, 0.f, 0.f);
#pragma unroll
            for (int c = 0; c < CEN; c++) {
                float4 cv = sC[c * D4 + cd];
#pragma unroll
                for (int r = 0; r < 4; r++) {
                    float p = phi_all[r][c];
                    acc[r].x += p * cv.x; acc[r].y += p * cv.y;
                    acc[r].z += p * cv.z; acc[r].w += p * cv.w;
                }
            }
#pragma unroll
            for (int r = 0; r < 4; r++)
                __stcs(&ct4[(size_t)(row0 + r) * D4 + cd], acc[r]);
        }
    } else {
        int am[4];
#pragma unroll
        for (int r = 0; r < 4; r++) {
            int a = 0; float bm = phi_all[r][0];
#pragma unroll
            for (int c = 1; c < CEN; c++)
                if (phi_all[r][c] > bm) { bm = phi_all[r][c]; a = c; }
            am[r] = a;
        }
#pragma unroll 2
        for (int k = 0; k < 24; k++) {
            int cd = k * 4 + q;
#pragma unroll
            for (int r = 0; r < 4; r++)
                __stcs(&ct4[(size_t)(row0 + r) * D4 + cd], sC[am[r] * D4 + cd]);
        }
    }

    // ---- colsum ----
    float colAcc[CEN];
#pragma unroll
    for (int c = 0; c < CEN; c++)
        colAcc[c] = (phi_all[0][c] + phi_all[1][c]) + (phi_all[2][c] + phi_all[3][c]);
#pragma unroll
    for (int o = 4; o <= 16; o <<= 1) {
#pragma unroll
        for (int c = 0; c < CEN; c++)
            colAcc[c] += __shfl_xor_sync(0xffffffffu, colAcc[c], o);
    }
    if (lane == 0) {
#pragma unroll
        for (int c = 0; c < CEN; c++) sred[wid][c] = colAcc[c];
    }
    __syncthreads();
    if (tid < CEN) {
        float s = 0.f;
#pragma unroll
        for (int wv = 0; wv < 4; wv++) s += sred[wv][tid];
        atomicAdd(&g_colsum[tid], s);
    }
}

// ---------------------------------------------------------------------------
// K3: cluster_target. TWO threads per row (131072 threads -> 2x warps/SM).
// Both threads of a pair load the full row (L2 broadcast); thread h=0 writes
// float2 slots 0,1,4; h=1 writes slots 2,3.
// ---------------------------------------------------------------------------
__global__ __launch_bounds__(256)
void k_target(float* __restrict__ out) {
    int idx = blockIdx.x * 256 + threadIdx.x;   // 0..131071
    int row = idx >> 1;
    int h   = idx & 1;

    const float2* p2 = (const float2*)(out + PHI_OFF + (size_t)row * CEN);
    float2 v0 = __ldg(p2 + 0), v1 = __ldg(p2 + 1), v2 = __ldg(p2 + 2),
           v3 = __ldg(p2 + 3), v4 = __ldg(p2 + 4);

    float cs[CEN];
#pragma unroll
    for (int c = 0; c < CEN; c++) cs[c] = g_colsum[c] + 1e-9f;

    float ph[CEN] = {v0.x, v0.y, v1.x, v1.y, v2.x, v2.y, v3.x, v3.y, v4.x, v4.y};
    float wv[CEN], s = 0.f;
#pragma unroll
    for (int c = 0; c < CEN; c++) {
        wv[c] = __fdividef(ph[c] * ph[c], cs[c]);
        s += wv[c];
    }
    float inv = __fdividef(1.f, s);
    float2* o2 = (float2*)(out + TGT_OFF + (size_t)row * CEN);
    if (h == 0) {
        o2[0] = make_float2(wv[0] * inv, wv[1] * inv);
        o2[1] = make_float2(wv[2] * inv, wv[3] * inv);
        o2[4] = make_float2(wv[8] * inv, wv[9] * inv);
    } else {
        o2[2] = make_float2(wv[4] * inv, wv[5] * inv);
        o2[3] = make_float2(wv[6] * inv, wv[7] * inv);
    }
}

// ---------------------------------------------------------------------------
extern "C" void kernel_launch(void* const* d_in, const int* in_sizes, int n_in,
                              void* d_out, int out_size) {
    const float* Ztd = (const float*)d_in[0];
    const float* M   = (const float*)d_in[1];
    const float* W1  = (const float*)d_in[2];
    const float* b1  = (const float*)d_in[3];
    const int*   wfl = (const int*)d_in[4];
    float* out = (float*)d_out;

    k_center1<<<24, 384>>>(M, W1);
    k_center2<<<15, 256>>>(b1);
    k_phi_ct<<<512, 128>>>(Ztd, out, wfl);
    k_target<<<512, 256>>>(out);
}

// round 16
// speedup vs baseline: 1.4261x; 1.4261x over previous
#include <cuda_runtime.h>

#define BATCH 65536
#define CEN   10
#define DIM   384
#define HID   768
#define D4    96

#define PHI_OFF ((size_t)BATCH * DIM)
#define TGT_OFF ((size_t)BATCH * DIM + (size_t)BATCH * CEN)

__device__ float  g_center[CEN * DIM];
__device__ float  g_colsum[CEN];
__device__ float4 g_part4[24 * CEN * D4];

// packed f32x2 helpers
#define FMA2(d, a, b, c_) \
    asm("fma.rn.f32x2 %0, %1, %2, %3;" : "=l"(d) : "l"(a), "l"(b), "l"(c_))
__device__ __forceinline__ float upk_sum(unsigned long long v) {
    float lo, hi;
    asm("mov.b64 {%0, %1}, %2;" : "=f"(lo), "=f"(hi) : "l"(v));
    return lo + hi;
}

// ---------------------------------------------------------------------------
// K1a: split-K partial GEMM for Center. 24 blocks x 384 threads. (R6 exact)
// ---------------------------------------------------------------------------
__global__ __launch_bounds__(384)
void k_center1(const float* __restrict__ M, const float* __restrict__ W1) {
    __shared__ float  sM[CEN][32];
    __shared__ float4 sAcc[4][CEN][D4];

    int tid = threadIdx.x;
    int hs  = tid / 96;
    int d4  = tid % 96;
    int h0  = blockIdx.x * 32;

    if (tid < 320) {
        int c = tid / 32, hl = tid % 32;
        sM[c][hl] = __ldg(M + c * HID + h0 + hl);
    }
    __syncthreads();

    float4 acc[CEN];
#pragma unroll
    for (int c = 0; c < CEN; c++) acc[c] = make_float4(0.f, 0.f, 0.f, 0.f);

    const float4* W4 = (const float4*)W1;
#pragma unroll
    for (int i = 0; i < 8; i++) {
        int hl = hs * 8 + i;
        float4 w = __ldg(&W4[(size_t)(h0 + hl) * D4 + d4]);
#pragma unroll
        for (int c = 0; c < CEN; c++) {
            float m = sM[c][hl];
            acc[c].x += m * w.x; acc[c].y += m * w.y;
            acc[c].z += m * w.z; acc[c].w += m * w.w;
        }
    }
#pragma unroll
    for (int c = 0; c < CEN; c++) sAcc[hs][c][d4] = acc[c];
    __syncthreads();

    if (hs == 0) {
#pragma unroll
        for (int c = 0; c < CEN; c++) {
            float4 a = sAcc[0][c][d4], b = sAcc[1][c][d4];
            float4 e = sAcc[2][c][d4], f = sAcc[3][c][d4];
            float4 s;
            s.x = (a.x + b.x) + (e.x + f.x);
            s.y = (a.y + b.y) + (e.y + f.y);
            s.z = (a.z + b.z) + (e.z + f.z);
            s.w = (a.w + b.w) + (e.w + f.w);
            g_part4[((size_t)blockIdx.x * CEN + c) * D4 + d4] = s;
        }
    }
}

// ---------------------------------------------------------------------------
// K1b: reduce partials + bias + LeakyReLU + /384; zero colsum. (R6 exact)
// ---------------------------------------------------------------------------
__global__ void k_center2(const float* __restrict__ b1) {
    int j = blockIdx.x * 256 + threadIdx.x;
    if (j < CEN * DIM) {
        const float* gp = (const float*)g_part4;
        float s = 0.f;
#pragma unroll
        for (int k = 0; k < 24; k++) s += gp[k * (CEN * DIM) + j];
        int d = j % DIM;
        float v = s + __ldg(b1 + d);
        v = (v >= 0.f) ? v : 0.01f * v;
        g_center[j] = v * (1.0f / 384.0f);
    }
    if (blockIdx.x == 0 && threadIdx.x < CEN) g_colsum[threadIdx.x] = 0.f;
}

// ---------------------------------------------------------------------------
// K2: phi + ct + colsum (R6 exact: R=4, 128 thr, 4 CTA/SM, plain-float ct,
// .cs streams, colsum last).
// ---------------------------------------------------------------------------
__global__ __launch_bounds__(128, 4)
void k_phi_ct(const float* __restrict__ Ztd, float* __restrict__ out,
              const int* __restrict__ weighted) {
    __shared__ float4 sC[CEN * D4];
    __shared__ float  scn[CEN];
    __shared__ float  sred[4][CEN];

    int tid = threadIdx.x, lane = tid & 31, wid = tid >> 5;
    int q = lane & 3;
    int g = lane >> 2;

    const float4* gc4 = (const float4*)g_center;
    for (int i = tid; i < CEN * D4; i += 128) sC[i] = gc4[i];
    __syncthreads();

    for (int c = wid; c < CEN; c += 4) {
        float s = 0.f;
#pragma unroll
        for (int k = 0; k < 3; k++) {
            float4 v = sC[c * D4 + lane + 32 * k];
            s += v.x * v.x + v.y * v.y + v.z * v.z + v.w * v.w;
        }
#pragma unroll
        for (int o = 16; o; o >>= 1) s += __shfl_xor_sync(0xffffffffu, s, o);
        if (lane == 0) scn[c] = s;
    }
    __syncthreads();

    int row0 = blockIdx.x * 128 + wid * 32 + g * 4;
    const char* Zb = (const char*)Ztd;
    const char* pr0 = Zb + ((size_t)(row0 + 0) * D4 + q) * 16;
    const char* pr1 = Zb + ((size_t)(row0 + 1) * D4 + q) * 16;
    const char* pr2 = Zb + ((size_t)(row0 + 2) * D4 + q) * 16;
    const char* pr3 = Zb + ((size_t)(row0 + 3) * D4 + q) * 16;
    const ulonglong2* sC2 = (const ulonglong2*)sC;

    unsigned long long dp2[4][CEN];
    unsigned long long zz2[4];
#pragma unroll
    for (int r = 0; r < 4; r++) {
        zz2[r] = 0ull;
#pragma unroll
        for (int c = 0; c < CEN; c++) dp2[r][c] = 0ull;
    }

#pragma unroll 4
    for (int k = 0; k < 24; k++) {
        unsigned long long za[4], zb[4];
        asm("ld.global.cs.v2.u64 {%0, %1}, [%2];" : "=l"(za[0]), "=l"(zb[0]) : "l"(pr0 + k * 64));
        asm("ld.global.cs.v2.u64 {%0, %1}, [%2];" : "=l"(za[1]), "=l"(zb[1]) : "l"(pr1 + k * 64));
        asm("ld.global.cs.v2.u64 {%0, %1}, [%2];" : "=l"(za[2]), "=l"(zb[2]) : "l"(pr2 + k * 64));
        asm("ld.global.cs.v2.u64 {%0, %1}, [%2];" : "=l"(za[3]), "=l"(zb[3]) : "l"(pr3 + k * 64));
#pragma unroll
        for (int r = 0; r < 4; r++) {
            FMA2(zz2[r], za[r], za[r], zz2[r]);
            FMA2(zz2[r], zb[r], zb[r], zz2[r]);
        }
#pragma unroll
        for (int c = 0; c < CEN; c++) {
            ulonglong2 cv = sC2[c * D4 + k * 4 + q];
#pragma unroll
            for (int r = 0; r < 4; r++) {
                FMA2(dp2[r][c], za[r], cv.x, dp2[r][c]);
                FMA2(dp2[r][c], zb[r], cv.y, dp2[r][c]);
            }
        }
    }

    float zz[4], dp[4][CEN];
#pragma unroll
    for (int r = 0; r < 4; r++) {
        zz[r] = upk_sum(zz2[r]);
#pragma unroll
        for (int c = 0; c < CEN; c++) dp[r][c] = upk_sum(dp2[r][c]);
    }

#pragma unroll
    for (int o = 1; o <= 2; o <<= 1) {
#pragma unroll
        for (int r = 0; r < 4; r++) {
            zz[r] += __shfl_xor_sync(0xffffffffu, zz[r], o);
#pragma unroll
            for (int c = 0; c < CEN; c++)
                dp[r][c] += __shfl_xor_sync(0xffffffffu, dp[r][c], o);
        }
    }

    float phi_all[4][CEN];
#pragma unroll
    for (int r = 0; r < 4; r++) {
        float nu[CEN], den = 0.f;
#pragma unroll
        for (int c = 0; c < CEN; c++) {
            float n = zz[r] - 2.f * dp[r][c] + scn[c];
            nu[c] = __fdividef(1.f, 1.f + n);
            den += nu[c];
        }
        float inv = __fdividef(1.f, den);
#pragma unroll
        for (int c = 0; c < CEN; c++) phi_all[r][c] = nu[c] * inv;

        float2* p2 = (float2*)(out + PHI_OFF + (size_t)(row0 + r) * CEN);
        p2[q] = make_float2(phi_all[r][2 * q], phi_all[r][2 * q + 1]);
        if (q == 0) p2[4] = make_float2(phi_all[r][8], phi_all[r][9]);
    }

    // ---- ct in-place ----
    float4* ct4 = (float4*)out;
    int w = *weighted;
    if (w) {
#pragma unroll 2
        for (int k = 0; k < 24; k++) {
            int cd = k * 4 + q;
            float4 acc[4];
#pragma unroll
            for (int r = 0; r < 4; r++) acc[r] = make_float4(0.f, 0.f, 0.f, 0.f);
#pragma unroll
            for (int c = 0; c < CEN; c++) {
                float4 cv = sC[c * D4 + cd];
#pragma unroll
                for (int r = 0; r < 4; r++) {
                    float p = phi_all[r][c];
                    acc[r].x += p * cv.x; acc[r].y += p * cv.y;
                    acc[r].z += p * cv.z; acc[r].w += p * cv.w;
                }
            }
#pragma unroll
            for (int r = 0; r < 4; r++)
                __stcs(&ct4[(size_t)(row0 + r) * D4 + cd], acc[r]);
        }
    } else {
        int am[4];
#pragma unroll
        for (int r = 0; r < 4; r++) {
            int a = 0; float bm = phi_all[r][0];
#pragma unroll
            for (int c = 1; c < CEN; c++)
                if (phi_all[r][c] > bm) { bm = phi_all[r][c]; a = c; }
            am[r] = a;
        }
#pragma unroll 2
        for (int k = 0; k < 24; k++) {
            int cd = k * 4 + q;
#pragma unroll
            for (int r = 0; r < 4; r++)
                __stcs(&ct4[(size_t)(row0 + r) * D4 + cd], sC[am[r] * D4 + cd]);
        }
    }

    // ---- colsum ----
    float colAcc[CEN];
#pragma unroll
    for (int c = 0; c < CEN; c++)
        colAcc[c] = (phi_all[0][c] + phi_all[1][c]) + (phi_all[2][c] + phi_all[3][c]);
#pragma unroll
    for (int o = 4; o <= 16; o <<= 1) {
#pragma unroll
        for (int c = 0; c < CEN; c++)
            colAcc[c] += __shfl_xor_sync(0xffffffffu, colAcc[c], o);
    }
    if (lane == 0) {
#pragma unroll
        for (int c = 0; c < CEN; c++) sred[wid][c] = colAcc[c];
    }
    __syncthreads();
    if (tid < CEN) {
        float s = 0.f;
#pragma unroll
        for (int wv = 0; wv < 4; wv++) s += sred[wv][tid];
        atomicAdd(&g_colsum[tid], s);
    }
}

// ---------------------------------------------------------------------------
// K3: cluster_target. TWO threads per row (131072 threads -> 2x warps/SM).
// Both threads of a pair load the full row (L2 broadcast); thread h=0 writes
// float2 slots 0,1,4; h=1 writes slots 2,3.
// ---------------------------------------------------------------------------
__global__ __launch_bounds__(256)
void k_target(float* __restrict__ out) {
    int idx = blockIdx.x * 256 + threadIdx.x;   // 0..131071
    int row = idx >> 1;
    int h   = idx & 1;

    const float2* p2 = (const float2*)(out + PHI_OFF + (size_t)row * CEN);
    float2 v0 = __ldg(p2 + 0), v1 = __ldg(p2 + 1), v2 = __ldg(p2 + 2),
           v3 = __ldg(p2 + 3), v4 = __ldg(p2 + 4);

    float cs[CEN];
#pragma unroll
    for (int c = 0; c < CEN; c++) cs[c] = g_colsum[c] + 1e-9f;

    float ph[CEN] = {v0.x, v0.y, v1.x, v1.y, v2.x, v2.y, v3.x, v3.y, v4.x, v4.y};
    float wv[CEN], s = 0.f;
#pragma unroll
    for (int c = 0; c < CEN; c++) {
        wv[c] = __fdividef(ph[c] * ph[c], cs[c]);
        s += wv[c];
    }
    float inv = __fdividef(1.f, s);
    float2* o2 = (float2*)(out + TGT_OFF + (size_t)row * CEN);
    if (h == 0) {
        o2[0] = make_float2(wv[0] * inv, wv[1] * inv);
        o2[1] = make_float2(wv[2] * inv, wv[3] * inv);
        o2[4] = make_float2(wv[8] * inv, wv[9] * inv);
    } else {
        o2[2] = make_float2(wv[4] * inv, wv[5] * inv);
        o2[3] = make_float2(wv[6] * inv, wv[7] * inv);
    }
}

// ---------------------------------------------------------------------------
extern "C" void kernel_launch(void* const* d_in, const int* in_sizes, int n_in,
                              void* d_out, int out_size) {
    const float* Ztd = (const float*)d_in[0];
    const float* M   = (const float*)d_in[1];
    const float* W1  = (const float*)d_in[2];
    const float* b1  = (const float*)d_in[3];
    const int*   wfl = (const int*)d_in[4];
    float* out = (float*)d_out;

    k_center1<<<24, 384>>>(M, W1);
    k_center2<<<15, 256>>>(b1);
    k_phi_ct<<<512, 128>>>(Ztd, out, wfl);
    k_target<<<512, 256>>>(out);
}